// round 8
// baseline (speedup 1.0000x reference)
#include <cuda_runtime.h>
#include <cuda_fp16.h>
#include <math.h>
#include <stdint.h>

// Problem constants
#define BB 8
#define SS 2048
#define DD 512
#define MFULL (BB * SS)          // 16384
#define INV_T (1.0f / 22.627416997969522f)
#define LN_EPS 1e-5f

// GEMM tiling: 128x128 block tile, K-slab 64 (halves), 3-stage cp.async
#define TKS 64
#define NSTAGE 3
#define RS 72                                  // row stride in halves (64 + 8 pad)
#define TILE_HALVES (128 * RS)                 // 9216
#define STAGE_HALVES (2 * TILE_HALVES)         // 18432
#define GEMM_SMEM_BYTES (NSTAGE * STAGE_HALVES * 2)   // 110592

// ---------------------------------------------------------------------------
// Scratch (device globals; no allocations allowed)
// ---------------------------------------------------------------------------
__device__ __half g_qh[MFULL * DD];
__device__ __half g_kh[MFULL * DD];
__device__ __half g_t1[MFULL * DD];
__device__ __half g_t2[MFULL * DD];
__device__ __half g_dq[MFULL * DD];
__device__ __half g_dk[MFULL * DD];
__device__ __half g_wt[6 * DD * DD];
__device__ __half g_vt[BB * DD * SS];
__device__ __half g_ah[(long long)BB * SS * SS];
__device__ int    g_mask_is_i32;

// ---------------------------------------------------------------------------
// helpers
// ---------------------------------------------------------------------------
__device__ __forceinline__ uint32_t smem_u32(const void* p) {
    uint32_t a;
    asm("{ .reg .u64 t; cvta.to.shared.u64 t, %1; cvt.u32.u64 %0, t; }" : "=r"(a) : "l"(p));
    return a;
}

__device__ __forceinline__ void mma_f16(float4& d,
    uint32_t a0, uint32_t a1, uint32_t a2, uint32_t a3,
    uint32_t b0, uint32_t b1)
{
    asm volatile(
        "mma.sync.aligned.m16n8k16.row.col.f32.f16.f16.f32 "
        "{%0,%1,%2,%3}, {%4,%5,%6,%7}, {%8,%9}, {%0,%1,%2,%3};\n"
        : "+f"(d.x), "+f"(d.y), "+f"(d.z), "+f"(d.w)
        : "r"(a0), "r"(a1), "r"(a2), "r"(a3), "r"(b0), "r"(b1));
}

#define LDMATRIX_X4(r0, r1, r2, r3, addr) \
    asm volatile("ldmatrix.sync.aligned.m8n8.x4.shared.b16 {%0,%1,%2,%3}, [%4];" \
        : "=r"(r0), "=r"(r1), "=r"(r2), "=r"(r3) : "r"(addr))

#define CP_ASYNC16(dst_u32, src_ptr) \
    asm volatile("cp.async.cg.shared.global [%0], [%1], 16;" \
        :: "r"(dst_u32), "l"(src_ptr) : "memory")
#define CP_COMMIT() asm volatile("cp.async.commit_group;" ::: "memory")
#define CP_WAIT(n)  asm volatile("cp.async.wait_group %0;" :: "n"(n) : "memory")

// ---------------------------------------------------------------------------
// Mask dtype detector
// ---------------------------------------------------------------------------
__global__ void detect_mask_kernel(const unsigned char* __restrict__ mb) {
    __shared__ int any;
    if (threadIdx.x == 0) any = 0;
    __syncthreads();
    for (int i = threadIdx.x; i < 4096; i += blockDim.x) {
        if ((i & 3) && mb[i]) atomicOr(&any, 1);
    }
    __syncthreads();
    if (threadIdx.x == 0) g_mask_is_i32 = any ? 0 : 1;
}

// ---------------------------------------------------------------------------
// fp32 -> fp16 elementwise convert (4 per thread)
// ---------------------------------------------------------------------------
__global__ void convert_h_kernel(const float* __restrict__ S, __half* __restrict__ D,
                                 long long n4) {
    const long long idx = (long long)blockIdx.x * blockDim.x + threadIdx.x;
    if (idx >= n4) return;
    const long long i = idx * 4;
    const float4 v = *(const float4*)(S + i);
    *(__half2*)(D + i)     = __floats2half2_rn(v.x, v.y);
    *(__half2*)(D + i + 2) = __floats2half2_rn(v.z, v.w);
}

// ---------------------------------------------------------------------------
// Tiled transpose with fp16 output: src fp32 [R][C] -> dst half [C][R]
// ---------------------------------------------------------------------------
__global__ void transpose_h_kernel(const float* __restrict__ S, __half* __restrict__ D,
                                   int R, int C, long long sS, long long sD) {
    __shared__ float tile[32][33];
    const float* s = S + (long long)blockIdx.z * sS;
    __half* d = D + (long long)blockIdx.z * sD;
    const int x = blockIdx.x * 32 + threadIdx.x;
    const int y0 = blockIdx.y * 32;
    #pragma unroll
    for (int i = threadIdx.y; i < 32; i += 8)
        tile[i][threadIdx.x] = s[(long long)(y0 + i) * C + x];
    __syncthreads();
    const int xo = blockIdx.y * 32 + threadIdx.x;
    const int yo0 = blockIdx.x * 32;
    #pragma unroll
    for (int i = threadIdx.y; i < 32; i += 8)
        d[(long long)(yo0 + i) * R + xo] = __float2half_rn(tile[threadIdx.x][i]);
}

// ===========================================================================
// Multistage fp16 mma.sync NT GEMM (fp32 accumulate) with ldmatrix frags:
//   C[m,n] = epilogue( sum_k A[m,k] * B[n,k] )
// A: half [M][K], B: half [N][K]. Block tile 128x128, 256 thr, 8 warps
// (4m x 2n), warp tile 32x64. K-slab 64, 3-stage cp.async.
// EPI: 0 = +bias+relu (half out), 1 = +bias (half out),
//      2 = QK mask/scale (float out), 3 = plain (float out)
// ===========================================================================
template<int EPI>
__global__ void __launch_bounds__(256, 2) gemm_h(
    const __half* __restrict__ Ag, const __half* __restrict__ Bg,
    const float* __restrict__ bias, void* __restrict__ Cg,
    int K, int ldc, long long sA, long long sB, long long sC,
    const void* __restrict__ maskp)
{
    extern __shared__ __half smh[];
    const uint32_t sbase = smem_u32(smh);
    const int tid  = threadIdx.x;
    const int warp = tid >> 5;
    const int lane = tid & 31;
    const int wm = (warp >> 1) * 32;
    const int wn = (warp & 1) * 64;

    const __half* A = Ag + (long long)blockIdx.z * sA;
    const __half* B = Bg + (long long)blockIdx.z * sB;
    const int bm = blockIdx.y * 128;
    const int bn = blockIdx.x * 128;

    // ldmatrix per-lane offsets (halves, relative to tile base):
    // x4 layout: lanes 0-7 -> matrix0 rows, 8-15 -> matrix1 (row+8),
    //            16-23 -> matrix2 (col+8), 24-31 -> matrix3 (row+8,col+8)
    const int lm_row = (lane & 7) + ((lane >> 3) & 1) * 8;
    const int lm_col = ((lane >> 4) & 1) * 8;
    uint32_t offA[2], offB[4];
    #pragma unroll
    for (int i = 0; i < 2; i++)
        offA[i] = (uint32_t)((wm + i * 16 + lm_row) * RS + lm_col);
    #pragma unroll
    for (int j2 = 0; j2 < 4; j2++)
        offB[j2] = (uint32_t)(TILE_HALVES + (wn + j2 * 16 + lm_row) * RS + lm_col);

    // cp.async loader: 128 rows x 64 halves per tile; A+B = 2048 16B-chunks;
    // 8 chunks/thread (4 A + 4 B).
    auto load_stage = [&](int t, int buf) {
        const __half* Abase = A + (long long)bm * K + t * TKS;
        const __half* Bbase = B + (long long)bn * K + t * TKS;
        const uint32_t s0 = sbase + (uint32_t)(buf * STAGE_HALVES) * 2u;
        #pragma unroll
        for (int i = 0; i < 4; i++) {
            const int c = tid + i * 256;
            const int m = c >> 3, kc = c & 7;
            CP_ASYNC16(s0 + (uint32_t)(m * RS + kc * 8) * 2u,
                       Abase + (long long)m * K + kc * 8);
            CP_ASYNC16(s0 + (uint32_t)(TILE_HALVES + m * RS + kc * 8) * 2u,
                       Bbase + (long long)m * K + kc * 8);
        }
    };

    float4 acc[2][8];
    #pragma unroll
    for (int i = 0; i < 2; i++)
        #pragma unroll
        for (int j = 0; j < 8; j++) acc[i][j] = make_float4(0.f, 0.f, 0.f, 0.f);

    const int T = K / TKS;

    load_stage(0, 0); CP_COMMIT();
    load_stage(1, 1); CP_COMMIT();

    for (int t = 0; t < T; t++) {
        const int buf = t % NSTAGE;
        CP_WAIT(1);                 // stage t resident
        __syncthreads();            // also orders compute(t-1) before buffer reuse
        if (t + 2 < T) load_stage(t + 2, (t + 2) % NSTAGE);
        CP_COMMIT();                // uniform group accounting

        const uint32_t base = sbase + (uint32_t)(buf * STAGE_HALVES) * 2u;

        #pragma unroll
        for (int ks = 0; ks < 4; ks++) {
            const uint32_t ck2 = (uint32_t)(ks * 16) * 2u;   // byte offset of k-chunk
            uint32_t af[2][4];
            LDMATRIX_X4(af[0][0], af[0][1], af[0][2], af[0][3], base + offA[0] * 2u + ck2);
            LDMATRIX_X4(af[1][0], af[1][1], af[1][2], af[1][3], base + offA[1] * 2u + ck2);
            #pragma unroll
            for (int j2 = 0; j2 < 4; j2++) {
                uint32_t m0, m1, m2, m3;
                LDMATRIX_X4(m0, m1, m2, m3, base + offB[j2] * 2u + ck2);
                // m0=(n,k0) m1=(n+8,k0) m2=(n,k8) m3=(n+8,k8)
                const int j = j2 * 2;
                mma_f16(acc[0][j],     af[0][0], af[0][1], af[0][2], af[0][3], m0, m2);
                mma_f16(acc[1][j],     af[1][0], af[1][1], af[1][2], af[1][3], m0, m2);
                mma_f16(acc[0][j + 1], af[0][0], af[0][1], af[0][2], af[0][3], m1, m3);
                mma_f16(acc[1][j + 1], af[1][0], af[1][1], af[1][2], af[1][3], m1, m3);
            }
        }
        // no trailing sync: top-of-loop barrier provides the ordering
    }

    // Epilogue: c0,c1 -> (r, c..c+1); c2,c3 -> (r+8, c..c+1)
    const int is_i32 = (EPI == 2) ? g_mask_is_i32 : 0;
    #pragma unroll
    for (int i = 0; i < 2; i++) {
        const int r0 = bm + wm + i * 16 + (lane >> 2);
        const int r1 = r0 + 8;
        #pragma unroll
        for (int j = 0; j < 8; j++) {
            const int c = bn + wn + j * 8 + (lane & 3) * 2;
            float2 v0 = make_float2(acc[i][j].x, acc[i][j].y);
            float2 v1 = make_float2(acc[i][j].z, acc[i][j].w);
            if (EPI == 0 || EPI == 1) {
                const float2 b = *(const float2*)(bias + c);
                v0.x += b.x; v0.y += b.y;
                v1.x += b.x; v1.y += b.y;
                if (EPI == 0) {
                    v0.x = fmaxf(v0.x, 0.f); v0.y = fmaxf(v0.y, 0.f);
                    v1.x = fmaxf(v1.x, 0.f); v1.y = fmaxf(v1.y, 0.f);
                }
                __half* C = (__half*)Cg + (long long)blockIdx.z * sC;
                *(__half2*)(C + (long long)r0 * ldc + c) = __floats2half2_rn(v0.x, v0.y);
                *(__half2*)(C + (long long)r1 * ldc + c) = __floats2half2_rn(v1.x, v1.y);
            } else {
                if (EPI == 2) {
                    const long long base2 = (long long)blockIdx.z * SS * SS;
                    const long long i00 = base2 + (long long)r0 * SS + c;
                    const long long i10 = base2 + (long long)r1 * SS + c;
                    bool m00, m01, m10, m11;
                    if (is_i32) {
                        const int* mi = (const int*)maskp;
                        m00 = mi[i00] != 0; m01 = mi[i00 + 1] != 0;
                        m10 = mi[i10] != 0; m11 = mi[i10 + 1] != 0;
                    } else {
                        const unsigned char* mu = (const unsigned char*)maskp;
                        m00 = mu[i00] != 0; m01 = mu[i00 + 1] != 0;
                        m10 = mu[i10] != 0; m11 = mu[i10 + 1] != 0;
                    }
                    v0.x = m00 ? -1e16f : v0.x * INV_T;
                    v0.y = m01 ? -1e16f : v0.y * INV_T;
                    v1.x = m10 ? -1e16f : v1.x * INV_T;
                    v1.y = m11 ? -1e16f : v1.y * INV_T;
                }
                float* C = (float*)Cg + (long long)blockIdx.z * sC;
                *(float2*)(C + (long long)r0 * ldc + c) = v0;
                *(float2*)(C + (long long)r1 * ldc + c) = v1;
            }
        }
    }
}

// ---------------------------------------------------------------------------
// Block reductions
// ---------------------------------------------------------------------------
__device__ __forceinline__ float blockReduceSum(float v, float* sh) {
    #pragma unroll
    for (int o = 16; o > 0; o >>= 1) v += __shfl_xor_sync(0xffffffffu, v, o);
    __syncthreads();
    if ((threadIdx.x & 31) == 0) sh[threadIdx.x >> 5] = v;
    __syncthreads();
    if (threadIdx.x < 32) {
        v = (threadIdx.x < (blockDim.x >> 5)) ? sh[threadIdx.x] : 0.0f;
        #pragma unroll
        for (int o = 16; o > 0; o >>= 1) v += __shfl_xor_sync(0xffffffffu, v, o);
        if (threadIdx.x == 0) sh[0] = v;
    }
    __syncthreads();
    return sh[0];
}

__device__ __forceinline__ float blockReduceMax(float v, float* sh) {
    #pragma unroll
    for (int o = 16; o > 0; o >>= 1) v = fmaxf(v, __shfl_xor_sync(0xffffffffu, v, o));
    __syncthreads();
    if ((threadIdx.x & 31) == 0) sh[threadIdx.x >> 5] = v;
    __syncthreads();
    if (threadIdx.x < 32) {
        v = (threadIdx.x < (blockDim.x >> 5)) ? sh[threadIdx.x] : -3.0e38f;
        #pragma unroll
        for (int o = 16; o > 0; o >>= 1) v = fmaxf(v, __shfl_xor_sync(0xffffffffu, v, o));
        if (threadIdx.x == 0) sh[0] = v;
    }
    __syncthreads();
    return sh[0];
}

// ---------------------------------------------------------------------------
// LayerNorm + ReLU: half in, half out (stats in fp32)
// ---------------------------------------------------------------------------
__global__ void ln_relu_h_kernel(const __half* __restrict__ X,
                                 const float* __restrict__ g,
                                 const float* __restrict__ beta,
                                 __half* __restrict__ Y)
{
    __shared__ float sh[32];
    const long long row = blockIdx.x;
    const __half* x = X + row * DD;
    const int t = threadIdx.x;

    const __half2 h0 = *(const __half2*)(x + t * 4);
    const __half2 h1 = *(const __half2*)(x + t * 4 + 2);
    const float2 f0 = __half22float2(h0);
    const float2 f1 = __half22float2(h1);
    float s  = f0.x + f0.y + f1.x + f1.y;
    float sq = f0.x * f0.x + f0.y * f0.y + f1.x * f1.x + f1.y * f1.y;
    s  = blockReduceSum(s, sh);
    sq = blockReduceSum(sq, sh);
    const float mu  = s * (1.0f / DD);
    const float var = sq * (1.0f / DD) - mu * mu;
    const float r = rsqrtf(var + LN_EPS);

    const float4 gv = *(const float4*)(g + t * 4);
    const float4 bv = *(const float4*)(beta + t * 4);
    float y0 = fmaxf((f0.x - mu) * r * gv.x + bv.x, 0.0f);
    float y1 = fmaxf((f0.y - mu) * r * gv.y + bv.y, 0.0f);
    float y2 = fmaxf((f1.x - mu) * r * gv.z + bv.z, 0.0f);
    float y3 = fmaxf((f1.y - mu) * r * gv.w + bv.w, 0.0f);
    *(__half2*)(Y + row * DD + t * 4)     = __floats2half2_rn(y0, y1);
    *(__half2*)(Y + row * DD + t * 4 + 2) = __floats2half2_rn(y2, y3);
}

// ---------------------------------------------------------------------------
// Negated softmax over rows of 2048, in place (fp32) + half mirror for PV.
// ---------------------------------------------------------------------------
__global__ void softmax_neg_kernel(float* __restrict__ P, __half* __restrict__ PH) {
    __shared__ float sh[32];
    float* p = P + (long long)blockIdx.x * SS;
    __half* ph = PH + (long long)blockIdx.x * SS;
    const int t = threadIdx.x;

    float4 x0 = *(float4*)(p + t * 8);
    float4 x1 = *(float4*)(p + t * 8 + 4);
    float mx = fmaxf(fmaxf(fmaxf(x0.x, x0.y), fmaxf(x0.z, x0.w)),
                     fmaxf(fmaxf(x1.x, x1.y), fmaxf(x1.z, x1.w)));
    mx = blockReduceMax(mx, sh);

    float e[8];
    e[0] = __expf(x0.x - mx); e[1] = __expf(x0.y - mx);
    e[2] = __expf(x0.z - mx); e[3] = __expf(x0.w - mx);
    e[4] = __expf(x1.x - mx); e[5] = __expf(x1.y - mx);
    e[6] = __expf(x1.z - mx); e[7] = __expf(x1.w - mx);
    float s = e[0] + e[1] + e[2] + e[3] + e[4] + e[5] + e[6] + e[7];
    s = blockReduceSum(s, sh);
    const float inv = -1.0f / s;

    x0.x = e[0] * inv; x0.y = e[1] * inv; x0.z = e[2] * inv; x0.w = e[3] * inv;
    x1.x = e[4] * inv; x1.y = e[5] * inv; x1.z = e[6] * inv; x1.w = e[7] * inv;
    *(float4*)(p + t * 8)     = x0;
    *(float4*)(p + t * 8 + 4) = x1;
    *(__half2*)(ph + t * 8)     = __floats2half2_rn(x0.x, x0.y);
    *(__half2*)(ph + t * 8 + 2) = __floats2half2_rn(x0.z, x0.w);
    *(__half2*)(ph + t * 8 + 4) = __floats2half2_rn(x1.x, x1.y);
    *(__half2*)(ph + t * 8 + 6) = __floats2half2_rn(x1.z, x1.w);
}

// ---------------------------------------------------------------------------
// Launch
// ---------------------------------------------------------------------------
extern "C" void kernel_launch(void* const* d_in, const int* in_sizes, int n_in,
                              void* d_out, int out_size)
{
    const float* q   = (const float*)d_in[0];
    const float* k   = (const float*)d_in[1];
    const float* v   = (const float*)d_in[2];
    const void*  mask = d_in[3];
    const float* qw1 = (const float*)d_in[4];
    const float* qw2 = (const float*)d_in[5];
    const float* qw3 = (const float*)d_in[6];
    const float* kw1 = (const float*)d_in[7];
    const float* kw2 = (const float*)d_in[8];
    const float* kw3 = (const float*)d_in[9];
    const float* qb1 = (const float*)d_in[10];
    const float* qb2 = (const float*)d_in[11];
    const float* qb3 = (const float*)d_in[12];
    const float* kb1 = (const float*)d_in[13];
    const float* kb2 = (const float*)d_in[14];
    const float* kb3 = (const float*)d_in[15];
    const float* q_ln_b = (const float*)d_in[16];
    const float* k_ln_b = (const float*)d_in[17];
    const float* q_ln_g = (const float*)d_in[18];
    const float* k_ln_g = (const float*)d_in[19];

    float* out  = (float*)d_out;                              // [B,S,D]
    float* attn = out + (long long)BB * SS * DD;              // [B,S,S]

    __half *qh, *kh, *t1, *t2, *dq, *dk, *wt, *vt, *ah;
    cudaGetSymbolAddress((void**)&qh, g_qh);
    cudaGetSymbolAddress((void**)&kh, g_kh);
    cudaGetSymbolAddress((void**)&t1, g_t1);
    cudaGetSymbolAddress((void**)&t2, g_t2);
    cudaGetSymbolAddress((void**)&dq, g_dq);
    cudaGetSymbolAddress((void**)&dk, g_dk);
    cudaGetSymbolAddress((void**)&wt, g_wt);
    cudaGetSymbolAddress((void**)&vt, g_vt);
    cudaGetSymbolAddress((void**)&ah, g_ah);

    const size_t shm = GEMM_SMEM_BYTES;
    cudaFuncSetAttribute(gemm_h<0>, cudaFuncAttributeMaxDynamicSharedMemorySize, shm);
    cudaFuncSetAttribute(gemm_h<1>, cudaFuncAttributeMaxDynamicSharedMemorySize, shm);
    cudaFuncSetAttribute(gemm_h<2>, cudaFuncAttributeMaxDynamicSharedMemorySize, shm);
    cudaFuncSetAttribute(gemm_h<3>, cudaFuncAttributeMaxDynamicSharedMemorySize, shm);

    detect_mask_kernel<<<1, 256>>>((const unsigned char*)mask);

    // fp32 -> fp16 inputs
    const long long n4 = (long long)MFULL * DD / 4;
    convert_h_kernel<<<(int)((n4 + 255) / 256), 256>>>(q, qh, n4);
    convert_h_kernel<<<(int)((n4 + 255) / 256), 256>>>(k, kh, n4);

    // Weights W[k][n] -> half Wt[n][k]
    const float* ws[6] = {qw1, qw2, qw3, kw1, kw2, kw3};
    for (int i = 0; i < 6; i++)
        transpose_h_kernel<<<dim3(16, 16, 1), dim3(32, 8)>>>(
            ws[i], wt + (long long)i * DD * DD, DD, DD, 0, 0);
    __half* wtq1 = wt + 0LL * DD * DD; __half* wtq2 = wt + 1LL * DD * DD;
    __half* wtq3 = wt + 2LL * DD * DD; __half* wtk1 = wt + 3LL * DD * DD;
    __half* wtk2 = wt + 4LL * DD * DD; __half* wtk3 = wt + 5LL * DD * DD;

    // V[b][t][d] -> half Vt[b][d][t]
    transpose_h_kernel<<<dim3(DD / 32, SS / 32, BB), dim3(32, 8)>>>(
        v, vt, SS, DD, (long long)SS * DD, (long long)DD * SS);

    const dim3 gMLP(DD / 128, MFULL / 128, 1);    // (4, 128, 1)

    // ---- deep_q ----
    gemm_h<0><<<gMLP, 256, shm>>>(qh, wtq1, qb1, t1, DD, DD, 0, 0, 0, nullptr);
    gemm_h<1><<<gMLP, 256, shm>>>(t1, wtq2, qb2, t2, DD, DD, 0, 0, 0, nullptr);
    ln_relu_h_kernel<<<MFULL, 128>>>(t2, q_ln_g, q_ln_b, t1);
    gemm_h<1><<<gMLP, 256, shm>>>(t1, wtq3, qb3, dq, DD, DD, 0, 0, 0, nullptr);

    // ---- deep_k ----
    gemm_h<0><<<gMLP, 256, shm>>>(kh, wtk1, kb1, t1, DD, DD, 0, 0, 0, nullptr);
    gemm_h<1><<<gMLP, 256, shm>>>(t1, wtk2, kb2, t2, DD, DD, 0, 0, 0, nullptr);
    ln_relu_h_kernel<<<MFULL, 128>>>(t2, k_ln_g, k_ln_b, t1);
    gemm_h<1><<<gMLP, 256, shm>>>(t1, wtk3, kb3, dk, DD, DD, 0, 0, 0, nullptr);

    // ---- attention ----
    gemm_h<2><<<dim3(SS / 128, SS / 128, BB), 256, shm>>>(
        dq, dk, nullptr, attn, DD, SS,
        (long long)SS * DD, (long long)SS * DD, (long long)SS * SS, mask);
    softmax_neg_kernel<<<MFULL, 256>>>(attn, ah);
    gemm_h<3><<<dim3(DD / 128, SS / 128, BB), 256, shm>>>(
        ah, vt, nullptr, out, SS, DD,
        (long long)SS * SS, (long long)DD * SS, (long long)SS * DD, nullptr);
}